// round 13
// baseline (speedup 1.0000x reference)
#include <cuda_runtime.h>
#include <cstdint>

// Problem constants
#define BB 4
#define LL 4096
#define DD 768
#define CHUNKS 128
#define ROWS 32            // LL / CHUNKS
#define SPAN 16            // output rows per write segment

// Scratch (device globals — no allocations allowed)
__device__ float g_partial[CHUNKS][BB][DD];   // per-chunk exp-weighted sums
__device__ float g_wsum[CHUNKS][BB];          // per-chunk exp-weight sums
__device__ float g_hbar[BB][DD];              // normalized probs·hs
__device__ float g_ctx[BB][DD];               // final context row (bias folded)
__device__ int   g_f1;                        // reduce-done counter (target 48)
__device__ int   g_f2;                        // gemv-done counter  (target 512)
__device__ int   g_fp;                        // pass counter for flag reset

__device__ __forceinline__ void spin_ge(const int* p, int target) {
    while (*(volatile const int*)p < target) __nanosleep(32);
}

// ---------------------------------------------------------------------------
// 1) wsum: partial[c][b][:] = Σ_{l in chunk, w(l)!=0} exp(mask[b,l])*hs[b,l,:]
//    mask is {0, -1e9} so weights are exactly {1, 0}: zero-weight rows are
//    SKIPPED (block-uniform branch). Unchanged from R12 (measured best).
// ---------------------------------------------------------------------------
__global__ void __launch_bounds__(192) wsum_kernel(const float* __restrict__ hs,
                                                   const float* __restrict__ mask) {
    const int t = threadIdx.x;                 // 192 = DD/4
    const int c = blockIdx.x;
    const int b = blockIdx.y;

    __shared__ float p[ROWS];
    if (t < ROWS) {                            // warp 0
        float w = expf(__ldg(&mask[(size_t)b * LL + c * ROWS + t]));
        p[t] = w;
        #pragma unroll
        for (int o = 16; o > 0; o >>= 1) w += __shfl_down_sync(0xffffffffu, w, o);
        if (t == 0) g_wsum[c][b] = w;
    }
    __syncthreads();

    const float4* __restrict__ src =
        (const float4*)(hs + ((size_t)b * LL + (size_t)c * ROWS) * DD);

    float4 acc = make_float4(0.f, 0.f, 0.f, 0.f);
    #pragma unroll 8
    for (int r = 0; r < ROWS; r++) {
        const float pr = p[r];
        if (pr != 0.0f) {                      // uniform branch: skip dead rows
            const float4 x = src[(size_t)r * (DD / 4) + t];
            acc.x = fmaf(pr, x.x, acc.x);
            acc.y = fmaf(pr, x.y, acc.y);
            acc.z = fmaf(pr, x.z, acc.z);
            acc.w = fmaf(pr, x.w, acc.w);
        }
    }
    ((float4*)g_partial[c][b])[t] = acc;
}

// ---------------------------------------------------------------------------
// 2) tail: reduce + gemv + bcast fused into ONE kernel (1024 blocks, 1 wave).
//    Blocks 0-47:  reduce -> hbar, release f1.
//    Blocks 0-511: spin f1, gemv (6 warps x 1 output) -> ctx, release f2.
//    All blocks:   spin f2, then the proven bcast write loop (unchanged).
//    Flags reset by the provably-last block (pass counter) -> deterministic.
// ---------------------------------------------------------------------------
__global__ void __launch_bounds__(192) tail_kernel(const float* __restrict__ Wv,
                                                   const float* __restrict__ bv,
                                                   float* __restrict__ out) {
#if __CUDA_ARCH__ >= 900
    cudaGridDependencySynchronize();           // PDL: wait for wsum's writes
#endif
    const int B = blockIdx.x;
    const int t = threadIdx.x;                 // 192

    __shared__ float  red[192];
    __shared__ float  s_invw;
    __shared__ __align__(16) float4 s_h4[DD / 4];

    // ---- Phase R: reduce (blocks 0..47; 64 outputs each) ------------------
    if (B < 48) {
        const int rb = B / 12;                 // batch (12 blocks per batch)
        if (t < 128) {                         // 2 threads per output
            const int oloc = t >> 1;           // 0..63
            const int half = t & 1;            // chunk half
            const int k = (B * 64 + oloc) % DD;
            float s = 0.0f;
            #pragma unroll 8
            for (int c = half * 64; c < half * 64 + 64; c++)
                s += g_partial[c][rb][k];
            red[t] = s;
        } else if (t >= 160) {                 // warp 5: 1/(total weight)
            const int lane = t - 160;
            float s = 0.0f;
            #pragma unroll
            for (int i = 0; i < CHUNKS / 32; i++) s += g_wsum[lane + 32 * i][rb];
            #pragma unroll
            for (int o = 16; o > 0; o >>= 1) s += __shfl_down_sync(0xffffffffu, s, o);
            if (lane == 0) s_invw = 1.0f / s;
        }
        __syncthreads();
        if (t < 128 && (t & 1) == 0) {
            const int oloc = t >> 1;
            g_hbar[rb][(B * 64 + oloc) % DD] = (red[t] + red[t + 1]) * s_invw;
        }
        __threadfence();
        __syncthreads();
        if (t == 0) atomicAdd(&g_f1, 1);
    }

    // ---- Phase G: gemv (blocks 0..511; 6 warps x 1 output) ----------------
    if (B < 512) {
        if (t == 0) spin_ge(&g_f1, 48);
        __syncthreads();
        __threadfence();
        const int gb = B / 128;                // batch (128 blocks per batch)
        s_h4[t] = __ldcg(&((const float4*)g_hbar[gb])[t]);
        __syncthreads();
        {
            const int w = t >> 5, lane = t & 31;
            const int d = (B * 6 + w) % DD;
            const float4* __restrict__ wv4 = (const float4*)(Wv + (size_t)d * DD);
            float acc = 0.0f;
            #pragma unroll
            for (int i = 0; i < 6; i++) {      // 192 float4 over 32 lanes
                const float4 wv = __ldg(&wv4[lane + 32 * i]);
                const float4 hv = s_h4[lane + 32 * i];
                acc = fmaf(wv.x, hv.x, fmaf(wv.y, hv.y,
                      fmaf(wv.z, hv.z, fmaf(wv.w, hv.w, acc))));
            }
            #pragma unroll
            for (int o = 16; o > 0; o >>= 1)
                acc += __shfl_down_sync(0xffffffffu, acc, o);
            if (lane == 0) g_ctx[gb][d] = acc + __ldg(&bv[d]);
        }
        __threadfence();
        __syncthreads();
        if (t == 0) atomicAdd(&g_f2, 1);
    }

    // ---- Phase W: broadcast write (all 1024 blocks; proven config) --------
    if (t == 0) spin_ge(&g_f2, 512);
    __syncthreads();
    __threadfence();
    const int b   = B >> 8;                    // 256 segments per batch
    const int seg = B & 255;
    const float4 v = __ldcg(&((const float4*)g_ctx[b])[t]);

    float4* __restrict__ dst =
        (float4*)(out + ((size_t)b * LL + (size_t)seg * SPAN) * DD);
    #pragma unroll
    for (int r = 0; r < SPAN; r++)
        __stcs(&dst[(size_t)r * (DD / 4) + t], v);

    // ---- Flag reset: the 1024th block to arrive is provably past all spins
    __syncthreads();
    if (t == 0) {
        const int r = atomicAdd(&g_fp, 1);
        if (r == 1023) { g_f1 = 0; g_f2 = 0; g_fp = 0; }
    }
}

// ---------------------------------------------------------------------------
// Launch helper — PDL-attributed launch for the dependent tail kernel.
// ---------------------------------------------------------------------------
template <typename K, typename... Args>
static inline void launch_pdl(K kern, dim3 grid, dim3 block, Args... args) {
    cudaLaunchConfig_t cfg = {};
    cfg.gridDim = grid;
    cfg.blockDim = block;
    cudaLaunchAttribute attr[1];
    attr[0].id = cudaLaunchAttributeProgrammaticStreamSerialization;
    attr[0].val.programmaticStreamSerializationAllowed = 1;
    cfg.attrs = attr;
    cfg.numAttrs = 1;
    cudaLaunchKernelEx(&cfg, kern, args...);
}

// ---------------------------------------------------------------------------
// Inputs: hidden_states, attention_mask, Wq, bq, Wk, bk, Wv, bv (Q/K dead)
// ---------------------------------------------------------------------------
extern "C" void kernel_launch(void* const* d_in, const int* in_sizes, int n_in,
                              void* d_out, int out_size) {
    const float* hs   = (const float*)d_in[0];
    const float* mask = (const float*)d_in[1];
    const float* Wv   = (const float*)d_in[6];
    const float* bv   = (const float*)d_in[7];
    float* out = (float*)d_out;

    wsum_kernel<<<dim3(CHUNKS, BB), 192>>>(hs, mask);
    launch_pdl(tail_kernel, dim3(1024), dim3(192), Wv, bv, out);
}

// round 14
// speedup vs baseline: 1.1940x; 1.1940x over previous
#include <cuda_runtime.h>
#include <cstdint>

// Problem constants
#define BB 4
#define LL 4096
#define DD 768
#define CHUNKS 128
#define ROWS 32            // LL / CHUNKS
#define KSPL 4             // gemv split-K factor
#define KS (DD / KSPL)     // 192 k-elements per slice
#define SPAN 16            // output rows per bcast block

// Scratch (device globals — zero-initialized at module load; bcast re-zeroes
// the accumulators at the end of every launch so each replay starts clean)
__device__ float g_hbar[BB][DD];              // UNNORMALIZED Σ exp(mask)·hs
__device__ float g_wtot[BB];                  // Σ exp(mask)
__device__ float g_ctx[BB][DD];               // final context row (bias folded)

// ---------------------------------------------------------------------------
// 1) wsum: each block computes its chunk's weighted partial in registers and
//    atomically accumulates it straight into g_hbar (reduce stage deleted).
//    mask is {0,-1e9} => weights exactly {1,0}: dead rows skipped (uniform
//    branch); softmax normalization deferred to gemv via g_wtot.
// ---------------------------------------------------------------------------
__global__ void __launch_bounds__(192) wsum_kernel(const float* __restrict__ hs,
                                                   const float* __restrict__ mask) {
    const int t = threadIdx.x;                 // 192 = DD/4
    const int c = blockIdx.x;
    const int b = blockIdx.y;

    __shared__ float p[ROWS];
    if (t < ROWS) {                            // warp 0
        float w = expf(__ldg(&mask[(size_t)b * LL + c * ROWS + t]));
        p[t] = w;
        #pragma unroll
        for (int o = 16; o > 0; o >>= 1) w += __shfl_down_sync(0xffffffffu, w, o);
        if (t == 0) atomicAdd(&g_wtot[b], w);
    }
    __syncthreads();

    const float4* __restrict__ src =
        (const float4*)(hs + ((size_t)b * LL + (size_t)c * ROWS) * DD);

    float4 acc = make_float4(0.f, 0.f, 0.f, 0.f);
    #pragma unroll 8
    for (int r = 0; r < ROWS; r++) {
        const float pr = p[r];
        if (pr != 0.0f) {                      // uniform branch: skip dead rows
            const float4 x = src[(size_t)r * (DD / 4) + t];
            acc.x = fmaf(pr, x.x, acc.x);
            acc.y = fmaf(pr, x.y, acc.y);
            acc.z = fmaf(pr, x.z, acc.z);
            acc.w = fmaf(pr, x.w, acc.w);
        }
    }
    // Accumulate chunk partial into g_hbar (4 scalar REDs per thread).
    float* __restrict__ h = g_hbar[b] + 4 * t;
    atomicAdd(h + 0, acc.x);
    atomicAdd(h + 1, acc.y);
    atomicAdd(h + 2, acc.z);
    atomicAdd(h + 3, acc.w);
}

// ---------------------------------------------------------------------------
// 2) gemv: ctx[b][d] = (hbar_unnorm[b,:]·Wv[d,:]) / wtot[b] + bv[d]
//    8 warps/block = 2 outputs x 4 k-slices; slice combine in smem.
//    Wv is L2-warm from the previous graph replay.
// ---------------------------------------------------------------------------
__global__ void __launch_bounds__(256) gemv_kernel(const float* __restrict__ Wv,
                                                   const float* __restrict__ bv) {
#if __CUDA_ARCH__ >= 900
    cudaGridDependencySynchronize();           // PDL: wait for wsum's atomics
#endif
    __shared__ float part[8];
    __shared__ float s_invw;
    const int w    = threadIdx.x >> 5;         // 0..7
    const int lane = threadIdx.x & 31;
    const int oidx = blockIdx.x * 2 + (w >> 2);  // 0..3071
    const int s    = w & 3;
    const int b    = oidx / DD, d = oidx % DD;

    if (threadIdx.x == 0) s_invw = 1.0f / g_wtot[blockIdx.x * 2 / DD];
    const float2* __restrict__ h2 = (const float2*)(g_hbar[b]) + s * (KS / 2);
    const float2* __restrict__ w2 = (const float2*)(Wv + (size_t)d * DD) + s * (KS / 2);

    float acc = 0.0f;
    #pragma unroll
    for (int i = 0; i < 3; i++) {              // KS/2 = 96 float2 over 32 lanes
        const float2 hv = h2[lane + 32 * i];
        const float2 wv = __ldg(&w2[lane + 32 * i]);
        acc = fmaf(hv.x, wv.x, fmaf(hv.y, wv.y, acc));
    }
    #pragma unroll
    for (int o = 16; o > 0; o >>= 1) acc += __shfl_down_sync(0xffffffffu, acc, o);
    if (lane == 0) part[w] = acc;
    __syncthreads();
    if (threadIdx.x < 2) {
        const int o2 = blockIdx.x * 2 + threadIdx.x;
        const float r = (part[threadIdx.x * 4] + part[threadIdx.x * 4 + 1] +
                         part[threadIdx.x * 4 + 2] + part[threadIdx.x * 4 + 3]) *
                        s_invw + __ldg(&bv[o2 % DD]);
        g_ctx[o2 / DD][o2 % DD] = r;
    }
}

// ---------------------------------------------------------------------------
// 3) bcast: out[b,l,:] = ctx[b,:] — measured-best config: scalar float4 STG,
//    16 rows/block, grid (256, BB); __stcs keeps output out of L2 residency.
//    Blocks with x==0 also re-zero the accumulators for the next replay
//    (safe: g_hbar/g_wtot are no longer read this launch; ctx is separate).
// ---------------------------------------------------------------------------
__global__ void __launch_bounds__(192) bcast_kernel(float* __restrict__ out) {
#if __CUDA_ARCH__ >= 900
    cudaGridDependencySynchronize();           // PDL: wait for gemv's writes
#endif
    const int b = blockIdx.y;
    const int t = threadIdx.x;                 // 192 = DD/4
    const float4 v = __ldg(&((const float4*)g_ctx[b])[t]);

    if (blockIdx.x == 0) {                     // reset accumulators for next replay
        ((float4*)g_hbar[b])[t] = make_float4(0.f, 0.f, 0.f, 0.f);
        if (t == 0) g_wtot[b] = 0.0f;
    }

    float4* __restrict__ dst =
        (float4*)(out + ((size_t)b * LL + (size_t)blockIdx.x * SPAN) * DD);
    #pragma unroll
    for (int r = 0; r < SPAN; r++)
        __stcs(&dst[(size_t)r * (DD / 4) + t], v);
}

// ---------------------------------------------------------------------------
// Launch helpers — PDL-attributed launches for the dependent kernels.
// ---------------------------------------------------------------------------
template <typename K, typename... Args>
static inline void launch_pdl(K kern, dim3 grid, dim3 block, Args... args) {
    cudaLaunchConfig_t cfg = {};
    cfg.gridDim = grid;
    cfg.blockDim = block;
    cudaLaunchAttribute attr[1];
    attr[0].id = cudaLaunchAttributeProgrammaticStreamSerialization;
    attr[0].val.programmaticStreamSerializationAllowed = 1;
    cfg.attrs = attr;
    cfg.numAttrs = 1;
    cudaLaunchKernelEx(&cfg, kern, args...);
}

// ---------------------------------------------------------------------------
// Inputs: hidden_states, attention_mask, Wq, bq, Wk, bk, Wv, bv (Q/K dead)
// ---------------------------------------------------------------------------
extern "C" void kernel_launch(void* const* d_in, const int* in_sizes, int n_in,
                              void* d_out, int out_size) {
    const float* hs   = (const float*)d_in[0];
    const float* mask = (const float*)d_in[1];
    const float* Wv   = (const float*)d_in[6];
    const float* bv   = (const float*)d_in[7];
    float* out = (float*)d_out;

    wsum_kernel<<<dim3(CHUNKS, BB), 192>>>(hs, mask);
    launch_pdl(gemv_kernel, dim3((BB * DD) / 2), dim3(256), Wv, bv);
    launch_pdl(bcast_kernel, dim3(LL / SPAN, BB), dim3(192), out);
}